// round 7
// baseline (speedup 1.0000x reference)
#include <cuda_runtime.h>
#include <cstdint>

#define NB   8
#define HH   64
#define WWD  64
#define LQ   4096
#define CHN  256
#define NCAT 384
#define MROWS (NB * LQ)           // 32768
#define KDIM 256
#define PADK 40                   // smem row stride (floats): conflict-free LDS.64
#define BUF_F (128 * PADK)        // 5120 floats per 128-row stage
#define GEMM_SMEM_BYTES (4 * BUF_F * 4)   // A0,A1,B0,B1 = 81920 B

// ---- scratch (device globals; no allocation allowed) ----
__device__ float g_bcat[NCAT];
__device__ float g_vom[(size_t)MROWS * NCAT];
__device__ float g_smp[(size_t)MROWS * CHN];
__device__ float g_bp1[NCAT * KDIM];   // GEMM-1 B, col-major [n][k], tf32-rounded
__device__ float g_bp2[CHN * KDIM];    // GEMM-2 B, col-major [n][k], tf32-rounded

__device__ __forceinline__ float tf32r(float x) {
    asm("cvt.rna.tf32.f32 %0, %0;" : "+f"(x));
    return x;
}
__device__ __forceinline__ void cpasync16(uint32_t dst, const float* src) {
    asm volatile("cp.async.ca.shared.global [%0], [%1], 16;"
                 :: "r"(dst), "l"(src));
}

// ---------------------------------------------------------------------------
// Pack weights (col-major, tf32-rounded) + concat biases.
// ---------------------------------------------------------------------------
__global__ void pack_weights(const float* __restrict__ wv, const float* __restrict__ bv,
                             const float* __restrict__ wo, const float* __restrict__ bo,
                             const float* __restrict__ wm, const float* __restrict__ bm,
                             const float* __restrict__ wout)
{
    int idx = blockIdx.x * 256 + threadIdx.x;
    if (idx < NCAT * KDIM) {
        int n = idx >> 8, k = idx & 255;
        float val = 0.f;
        if (n < 256)      val = wv[k * 256 + n];
        else if (n < 328) val = wo[k * 72 + (n - 256)];
        else if (n < 364) val = wm[k * 36 + (n - 328)];
        g_bp1[idx] = tf32r(val);
    } else if (idx < NCAT * KDIM + CHN * KDIM) {
        int j = idx - NCAT * KDIM;
        int n = j >> 8, k = j & 255;
        g_bp2[j] = tf32r(wout[k * 256 + n]);
    } else if (idx < NCAT * KDIM + CHN * KDIM + NCAT) {
        int c = idx - (NCAT * KDIM + CHN * KDIM);
        float val = 0.f;
        if (c < 256)      val = bv[c];
        else if (c < 328) val = bo[c - 256];
        else if (c < 364) val = bm[c - 328];
        g_bcat[c] = val;
    }
}

// ---------------------------------------------------------------------------
// tf32 mma.sync GEMM. CTA 128x128, 8 warps (4m x 2n), warp 32x64, BK=32.
// cp.async double-buffered, one sync per chunk. Fragments via LDS.64 using
// k-slot permutation (slot tg <-> k=kb+2tg, slot tg+4 <-> k=kb+2tg+1), applied
// identically to A and B so the mma result is unchanged.
// ---------------------------------------------------------------------------
template<int ROUND_A>
__global__ __launch_bounds__(256, 2) void gemm_mma(const float* __restrict__ A,
                                                   const float* __restrict__ Bcm,
                                                   const float* __restrict__ bias,
                                                   float* __restrict__ C, int ldc)
{
    extern __shared__ float smem[];
    uint32_t sbase = (uint32_t)__cvta_generic_to_shared(smem);

    int tid = threadIdx.x;
    int warp = tid >> 5, lane = tid & 31;
    int wmi = warp >> 1;          // 0..3 (M, 32-row tiles)
    int wni = warp & 1;           // 0..1 (N, 64-col tiles)
    int gid = lane >> 2, tg = lane & 3;

    const float* Ab = A   + (size_t)blockIdx.y * 128 * KDIM;
    const float* Bb = Bcm + (size_t)blockIdx.x * 128 * KDIM;

    int r0 = tid >> 3, q0 = (tid & 7) * 4;

    float acc[2][8][4];
#pragma unroll
    for (int mt = 0; mt < 2; ++mt)
#pragma unroll
        for (int nt = 0; nt < 8; ++nt)
#pragma unroll
            for (int i = 0; i < 4; ++i) acc[mt][nt][i] = 0.f;

    auto issue = [&](int c, int b) {
        uint32_t adst = sbase + (uint32_t)(b * BUF_F) * 4;
        uint32_t bdst = sbase + (uint32_t)((2 + b) * BUF_F) * 4;
        const float* asrc = Ab + c * 32;
        const float* bsrc = Bb + c * 32;
#pragma unroll
        for (int j = 0; j < 4; ++j) {
            int r = r0 + j * 32;
            cpasync16(adst + (uint32_t)(r * PADK + q0) * 4, asrc + (size_t)r * KDIM + q0);
        }
#pragma unroll
        for (int j = 0; j < 4; ++j) {
            int r = r0 + j * 32;
            cpasync16(bdst + (uint32_t)(r * PADK + q0) * 4, bsrc + (size_t)r * KDIM + q0);
        }
        asm volatile("cp.async.commit_group;" ::: "memory");
    };

    issue(0, 0);

    for (int c = 0; c < 8; ++c) {
        int b = c & 1;
        asm volatile("cp.async.wait_group 0;" ::: "memory");
        __syncthreads();                      // tile c visible; all warps done with c-1
        if (c < 7) issue(c + 1, b ^ 1);       // prefetch overlaps compute(c)

        const float* As = smem + b * BUF_F;
        const float* Bs = smem + (2 + b) * BUF_F;
#pragma unroll
        for (int ks = 0; ks < 4; ++ks) {
            int kb = ks * 8;
            uint32_t a[2][4], bf[8][2];
#pragma unroll
            for (int mt = 0; mt < 2; ++mt) {
                int row = wmi * 32 + mt * 16;
                float2 e0 = *(const float2*)&As[(row + gid) * PADK + kb + 2 * tg];
                float2 e1 = *(const float2*)&As[(row + gid + 8) * PADK + kb + 2 * tg];
                if (ROUND_A) {
                    e0.x = tf32r(e0.x); e0.y = tf32r(e0.y);
                    e1.x = tf32r(e1.x); e1.y = tf32r(e1.y);
                }
                a[mt][0] = __float_as_uint(e0.x);   // slot tg     (k = kb+2tg)
                a[mt][1] = __float_as_uint(e1.x);
                a[mt][2] = __float_as_uint(e0.y);   // slot tg+4   (k = kb+2tg+1)
                a[mt][3] = __float_as_uint(e1.y);
            }
#pragma unroll
            for (int nt = 0; nt < 8; ++nt) {
                int n = wni * 64 + nt * 8 + gid;
                float2 e = *(const float2*)&Bs[n * PADK + kb + 2 * tg];
                bf[nt][0] = __float_as_uint(e.x);
                bf[nt][1] = __float_as_uint(e.y);
            }
#pragma unroll
            for (int mt = 0; mt < 2; ++mt)
#pragma unroll
                for (int nt = 0; nt < 8; ++nt) {
                    asm volatile(
                        "mma.sync.aligned.m16n8k8.row.col.f32.tf32.tf32.f32 "
                        "{%0,%1,%2,%3}, {%4,%5,%6,%7}, {%8,%9}, {%0,%1,%2,%3};"
                        : "+f"(acc[mt][nt][0]), "+f"(acc[mt][nt][1]),
                          "+f"(acc[mt][nt][2]), "+f"(acc[mt][nt][3])
                        : "r"(a[mt][0]), "r"(a[mt][1]), "r"(a[mt][2]), "r"(a[mt][3]),
                          "r"(bf[nt][0]), "r"(bf[nt][1]));
                }
        }
    }

#pragma unroll
    for (int mt = 0; mt < 2; ++mt) {
#pragma unroll
        for (int i = 0; i < 2; ++i) {
            size_t row = (size_t)blockIdx.y * 128 + wmi * 32 + mt * 16 + gid + i * 8;
            float* Crow = C + row * (size_t)ldc;
#pragma unroll
            for (int nt = 0; nt < 8; ++nt) {
                int col = blockIdx.x * 128 + wni * 64 + nt * 8 + 2 * tg;
                float2 o;
                o.x = acc[mt][nt][2 * i + 0] + bias[col + 0];
                o.y = acc[mt][nt][2 * i + 1] + bias[col + 1];
                *(float2*)(&Crow[col]) = o;
            }
        }
    }
}

// ---------------------------------------------------------------------------
// DCNv4 bilinear sampling (unchanged). 4 queries per 256-thread block.
// ---------------------------------------------------------------------------
__global__ __launch_bounds__(256) void dcn_sample(const float* __restrict__ vom,
                                                  float* __restrict__ smp)
{
    int tid = threadIdx.x;
    int qbase = blockIdx.x * 4;

    __shared__ float4 s_wgt[4][4][9];
    __shared__ int4   s_idx[4][4][9];

    if (tid < 144) {
        int qq = tid / 36, u = tid % 36;
        int g = u / 9, p = u % 9;
        int q = qbase + qq;
        int hw = q & 4095, h = hw >> 6, w = hw & 63;
        const float* row = vom + (size_t)q * NCAT;
        float ox = row[256 + g * 18 + p * 2];
        float oy = row[256 + g * 18 + p * 2 + 1];
        float m  = row[328 + g * 9 + p];

        int ix = p / 3, iy = p % 3;
        float gx = (float)(w + ix - 1) + ox;
        float gy = (float)(h + iy - 1) + oy;

        float x0f = floorf(gx), y0f = floorf(gy);
        int x0 = (int)x0f, y0 = (int)y0f;
        float wx = gx - x0f, wy = gy - y0f;

        float vx0 = (x0 >= 0 && x0 < WWD) ? 1.f : 0.f;
        float vx1 = (x0 + 1 >= 0 && x0 + 1 < WWD) ? 1.f : 0.f;
        float vy0 = (y0 >= 0 && y0 < HH) ? 1.f : 0.f;
        float vy1 = (y0 + 1 >= 0 && y0 + 1 < HH) ? 1.f : 0.f;

        float4 W;
        W.x = (1.f - wx) * (1.f - wy) * m * vx0 * vy0;
        W.y = wx * (1.f - wy) * m * vx1 * vy0;
        W.z = (1.f - wx) * wy * m * vx0 * vy1;
        W.w = wx * wy * m * vx1 * vy1;

        int x0c = min(max(x0, 0), WWD - 1);
        int x1c = min(max(x0 + 1, 0), WWD - 1);
        int y0c = min(max(y0, 0), HH - 1);
        int y1c = min(max(y0 + 1, 0), HH - 1);

        int4 O;
        O.x = (y0c * WWD + x0c) * (NCAT * 4);
        O.y = (y0c * WWD + x1c) * (NCAT * 4);
        O.z = (y1c * WWD + x0c) * (NCAT * 4);
        O.w = (y1c * WWD + x1c) * (NCAT * 4);

        s_wgt[qq][g][p] = W;
        s_idx[qq][g][p] = O;
    }
    __syncthreads();

    int qi = tid >> 6;
    int s  = tid & 63;
    int g  = s >> 4;
    int c4 = s & 15;
    int q = qbase + qi;
    int n = q >> 12;

    const char* vb = (const char*)(vom + (size_t)(n * LQ) * NCAT + g * 64 + c4 * 4);

    float4 acc = make_float4(0.f, 0.f, 0.f, 0.f);
#pragma unroll
    for (int p = 0; p < 9; ++p) {
        float4 W = s_wgt[qi][g][p];
        int4   O = s_idx[qi][g][p];

        float4 v00 = *(const float4*)(vb + O.x);
        float4 v10 = *(const float4*)(vb + O.y);
        float4 v01 = *(const float4*)(vb + O.z);
        float4 v11 = *(const float4*)(vb + O.w);

        acc.x = fmaf(W.x, v00.x, acc.x); acc.y = fmaf(W.x, v00.y, acc.y);
        acc.z = fmaf(W.x, v00.z, acc.z); acc.w = fmaf(W.x, v00.w, acc.w);
        acc.x = fmaf(W.y, v10.x, acc.x); acc.y = fmaf(W.y, v10.y, acc.y);
        acc.z = fmaf(W.y, v10.z, acc.z); acc.w = fmaf(W.y, v10.w, acc.w);
        acc.x = fmaf(W.z, v01.x, acc.x); acc.y = fmaf(W.z, v01.y, acc.y);
        acc.z = fmaf(W.z, v01.z, acc.z); acc.w = fmaf(W.z, v01.w, acc.w);
        acc.x = fmaf(W.w, v11.x, acc.x); acc.y = fmaf(W.w, v11.y, acc.y);
        acc.z = fmaf(W.w, v11.z, acc.z); acc.w = fmaf(W.w, v11.w, acc.w);
    }

    acc.x = tf32r(acc.x); acc.y = tf32r(acc.y);
    acc.z = tf32r(acc.z); acc.w = tf32r(acc.w);
    *(float4*)(smp + (size_t)q * CHN + g * 64 + c4 * 4) = acc;
}

// ---------------------------------------------------------------------------
extern "C" void kernel_launch(void* const* d_in, const int* in_sizes, int n_in,
                              void* d_out, int out_size)
{
    const float* x        = (const float*)d_in[0];
    const float* w_value  = (const float*)d_in[1];
    const float* b_value  = (const float*)d_in[2];
    const float* w_offset = (const float*)d_in[3];
    const float* b_offset = (const float*)d_in[4];
    const float* w_mask   = (const float*)d_in[5];
    const float* b_mask   = (const float*)d_in[6];
    const float* w_out    = (const float*)d_in[7];
    const float* b_out    = (const float*)d_in[8];
    float* out = (float*)d_out;

    float *vom, *smp, *bcat, *bp1, *bp2;
    cudaGetSymbolAddress((void**)&vom,  g_vom);
    cudaGetSymbolAddress((void**)&smp,  g_smp);
    cudaGetSymbolAddress((void**)&bcat, g_bcat);
    cudaGetSymbolAddress((void**)&bp1,  g_bp1);
    cudaGetSymbolAddress((void**)&bp2,  g_bp2);

    cudaFuncSetAttribute(gemm_mma<1>, cudaFuncAttributeMaxDynamicSharedMemorySize,
                         GEMM_SMEM_BYTES);
    cudaFuncSetAttribute(gemm_mma<0>, cudaFuncAttributeMaxDynamicSharedMemorySize,
                         GEMM_SMEM_BYTES);

    int pack_elems = NCAT * KDIM + CHN * KDIM + NCAT;
    pack_weights<<<(pack_elems + 255) / 256, 256>>>(w_value, b_value, w_offset,
                                                    b_offset, w_mask, b_mask, w_out);

    // GEMM-1: x(32768,256) @ [wv|wo|wm](256,384) + bcat -> vom (ldc=384); rounds A
    gemm_mma<1><<<dim3(NCAT / 128, MROWS / 128), 256, GEMM_SMEM_BYTES>>>(x, bp1, bcat,
                                                                         vom, NCAT);

    // DCNv4 sampling -> smp(32768,256), tf32-rounded on store
    dcn_sample<<<MROWS / 4, 256>>>(vom, smp);

    // GEMM-2: smp(32768,256) @ w_out(256,256) + b_out -> out (ldc=256)
    gemm_mma<0><<<dim3(CHN / 128, MROWS / 128), 256, GEMM_SMEM_BYTES>>>(smp, bp2, b_out,
                                                                        out, CHN);
}

// round 8
// speedup vs baseline: 1.0319x; 1.0319x over previous
#include <cuda_runtime.h>
#include <cstdint>

#define NB   8
#define HH   64
#define WWD  64
#define LQ   4096
#define CHN  256
#define NCAT 384
#define MROWS (NB * LQ)           // 32768
#define KDIM 256
#define PADK 36                   // smem row stride (floats)
#define BUF_A (256 * PADK)        // 9216 floats per A stage (256 rows)
#define BUF_B (128 * PADK)        // 4608 floats per B stage (128 n-rows)
#define STAGES 3
#define GEMM_SMEM_BYTES (STAGES * (BUF_A + BUF_B) * 4)   // 165888 B

// ---- scratch (device globals; no allocation allowed) ----
__device__ float g_bcat[NCAT];
__device__ float g_vom[(size_t)MROWS * NCAT];
__device__ float g_smp[(size_t)MROWS * CHN];
__device__ float g_bp1[NCAT * KDIM];   // GEMM-1 B, col-major [n][k], tf32-rounded
__device__ float g_bp2[CHN * KDIM];    // GEMM-2 B, col-major [n][k], tf32-rounded

__device__ __forceinline__ float tf32r(float x) {
    asm("cvt.rna.tf32.f32 %0, %0;" : "+f"(x));
    return x;
}
__device__ __forceinline__ void cpasync16(uint32_t dst, const float* src) {
    asm volatile("cp.async.ca.shared.global [%0], [%1], 16;"
                 :: "r"(dst), "l"(src));
}

// ---------------------------------------------------------------------------
// Pack weights (col-major, tf32-rounded) + concat biases.
// ---------------------------------------------------------------------------
__global__ void pack_weights(const float* __restrict__ wv, const float* __restrict__ bv,
                             const float* __restrict__ wo, const float* __restrict__ bo,
                             const float* __restrict__ wm, const float* __restrict__ bm,
                             const float* __restrict__ wout)
{
    int idx = blockIdx.x * 256 + threadIdx.x;
    if (idx < NCAT * KDIM) {
        int n = idx >> 8, k = idx & 255;
        float val = 0.f;
        if (n < 256)      val = wv[k * 256 + n];
        else if (n < 328) val = wo[k * 72 + (n - 256)];
        else if (n < 364) val = wm[k * 36 + (n - 328)];
        g_bp1[idx] = tf32r(val);
    } else if (idx < NCAT * KDIM + CHN * KDIM) {
        int j = idx - NCAT * KDIM;
        int n = j >> 8, k = j & 255;
        g_bp2[j] = tf32r(wout[k * 256 + n]);
    } else if (idx < NCAT * KDIM + CHN * KDIM + NCAT) {
        int c = idx - (NCAT * KDIM + CHN * KDIM);
        float val = 0.f;
        if (c < 256)      val = bv[c];
        else if (c < 328) val = bo[c - 256];
        else if (c < 364) val = bm[c - 328];
        g_bcat[c] = val;
    }
}

// ---------------------------------------------------------------------------
// tf32 mma.sync GEMM: 3-stage cp.async ring, one sync per K-chunk.
// C(M,N) = A(M,256) @ B^T + bias. B col-major pre-rounded.
// ROUND_A=1: tf32-round A fragments after LDS (raw fp32 A input).
// CTA tile 256x128, 8 warps (4m x 2n), warp tile 64x64, BK=32.
// ---------------------------------------------------------------------------
template<int ROUND_A>
__global__ __launch_bounds__(256) void gemm_mma(const float* __restrict__ A,
                                                const float* __restrict__ Bcm,
                                                const float* __restrict__ bias,
                                                float* __restrict__ C, int ldc)
{
    extern __shared__ float smem[];
    uint32_t sbase = (uint32_t)__cvta_generic_to_shared(smem);

    int tid = threadIdx.x;
    int warp = tid >> 5, lane = tid & 31;
    int wmi = warp >> 1;          // 0..3 (M, 64-row tiles)
    int wni = warp & 1;           // 0..1 (N, 64-col tiles)
    int gid = lane >> 2, tg = lane & 3;

    const float* Ab = A   + (size_t)blockIdx.y * 256 * KDIM;
    const float* Bb = Bcm + (size_t)blockIdx.x * 128 * KDIM;

    int r0 = tid >> 3, q0 = (tid & 7) * 4;   // slot base: row r0 (+32 per j), quad q0

    float acc[4][8][4];
#pragma unroll
    for (int mt = 0; mt < 4; ++mt)
#pragma unroll
        for (int nt = 0; nt < 8; ++nt)
#pragma unroll
            for (int i = 0; i < 4; ++i) acc[mt][nt][i] = 0.f;

    auto issue = [&](int c, int st) {
        uint32_t adst = sbase + (uint32_t)(st * BUF_A) * 4;
        uint32_t bdst = sbase + (uint32_t)(STAGES * BUF_A + st * BUF_B) * 4;
        const float* asrc = Ab + c * 32;
        const float* bsrc = Bb + c * 32;
#pragma unroll
        for (int j = 0; j < 8; ++j) {        // A: 256 rows x 32 k
            int r = r0 + j * 32;
            cpasync16(adst + (uint32_t)(r * PADK + q0) * 4, asrc + (size_t)r * KDIM + q0);
        }
#pragma unroll
        for (int j = 0; j < 4; ++j) {        // B: 128 n x 32 k
            int r = r0 + j * 32;
            cpasync16(bdst + (uint32_t)(r * PADK + q0) * 4, bsrc + (size_t)r * KDIM + q0);
        }
        asm volatile("cp.async.commit_group;" ::: "memory");
    };

    issue(0, 0);
    issue(1, 1);

    for (int c = 0; c < 8; ++c) {
        int st = c % STAGES;
        if (c < 7) {
            asm volatile("cp.async.wait_group 1;" ::: "memory");   // group c done
        } else {
            asm volatile("cp.async.wait_group 0;" ::: "memory");
        }
        __syncthreads();                      // tile c visible; all warps done with c-2's stage
        if (c + 2 < 8) issue(c + 2, (c + 2) % STAGES);   // 2 loads in flight over compute(c)

        const float* As = smem + st * BUF_A;
        const float* Bs = smem + STAGES * BUF_A + st * BUF_B;
#pragma unroll
        for (int ks = 0; ks < 4; ++ks) {
            int kb = ks * 8;
            uint32_t a[4][4], bf[8][2];
#pragma unroll
            for (int mt = 0; mt < 4; ++mt) {
                int row = wmi * 64 + mt * 16;
                float a0 = As[(row + gid) * PADK + kb + tg];
                float a1 = As[(row + gid + 8) * PADK + kb + tg];
                float a2 = As[(row + gid) * PADK + kb + tg + 4];
                float a3 = As[(row + gid + 8) * PADK + kb + tg + 4];
                if (ROUND_A) { a0 = tf32r(a0); a1 = tf32r(a1); a2 = tf32r(a2); a3 = tf32r(a3); }
                a[mt][0] = __float_as_uint(a0);
                a[mt][1] = __float_as_uint(a1);
                a[mt][2] = __float_as_uint(a2);
                a[mt][3] = __float_as_uint(a3);
            }
#pragma unroll
            for (int nt = 0; nt < 8; ++nt) {
                int n = wni * 64 + nt * 8 + gid;
                bf[nt][0] = __float_as_uint(Bs[n * PADK + kb + tg]);
                bf[nt][1] = __float_as_uint(Bs[n * PADK + kb + tg + 4]);
            }
#pragma unroll
            for (int mt = 0; mt < 4; ++mt)
#pragma unroll
                for (int nt = 0; nt < 8; ++nt) {
                    asm volatile(
                        "mma.sync.aligned.m16n8k8.row.col.f32.tf32.tf32.f32 "
                        "{%0,%1,%2,%3}, {%4,%5,%6,%7}, {%8,%9}, {%0,%1,%2,%3};"
                        : "+f"(acc[mt][nt][0]), "+f"(acc[mt][nt][1]),
                          "+f"(acc[mt][nt][2]), "+f"(acc[mt][nt][3])
                        : "r"(a[mt][0]), "r"(a[mt][1]), "r"(a[mt][2]), "r"(a[mt][3]),
                          "r"(bf[nt][0]), "r"(bf[nt][1]));
                }
        }
    }

#pragma unroll
    for (int mt = 0; mt < 4; ++mt) {
#pragma unroll
        for (int i = 0; i < 2; ++i) {
            size_t row = (size_t)blockIdx.y * 256 + wmi * 64 + mt * 16 + gid + i * 8;
            float* Crow = C + row * (size_t)ldc;
#pragma unroll
            for (int nt = 0; nt < 8; ++nt) {
                int col = blockIdx.x * 128 + wni * 64 + nt * 8 + 2 * tg;
                float2 o;
                o.x = acc[mt][nt][2 * i + 0] + bias[col + 0];
                o.y = acc[mt][nt][2 * i + 1] + bias[col + 1];
                *(float2*)(&Crow[col]) = o;
            }
        }
    }
}

// ---------------------------------------------------------------------------
// DCNv4 bilinear sampling (unchanged). 4 queries per 256-thread block.
// ---------------------------------------------------------------------------
__global__ __launch_bounds__(256) void dcn_sample(const float* __restrict__ vom,
                                                  float* __restrict__ smp)
{
    int tid = threadIdx.x;
    int qbase = blockIdx.x * 4;

    __shared__ float4 s_wgt[4][4][9];
    __shared__ int4   s_idx[4][4][9];

    if (tid < 144) {
        int qq = tid / 36, u = tid % 36;
        int g = u / 9, p = u % 9;
        int q = qbase + qq;
        int hw = q & 4095, h = hw >> 6, w = hw & 63;
        const float* row = vom + (size_t)q * NCAT;
        float ox = row[256 + g * 18 + p * 2];
        float oy = row[256 + g * 18 + p * 2 + 1];
        float m  = row[328 + g * 9 + p];

        int ix = p / 3, iy = p % 3;
        float gx = (float)(w + ix - 1) + ox;
        float gy = (float)(h + iy - 1) + oy;

        float x0f = floorf(gx), y0f = floorf(gy);
        int x0 = (int)x0f, y0 = (int)y0f;
        float wx = gx - x0f, wy = gy - y0f;

        float vx0 = (x0 >= 0 && x0 < WWD) ? 1.f : 0.f;
        float vx1 = (x0 + 1 >= 0 && x0 + 1 < WWD) ? 1.f : 0.f;
        float vy0 = (y0 >= 0 && y0 < HH) ? 1.f : 0.f;
        float vy1 = (y0 + 1 >= 0 && y0 + 1 < HH) ? 1.f : 0.f;

        float4 W;
        W.x = (1.f - wx) * (1.f - wy) * m * vx0 * vy0;
        W.y = wx * (1.f - wy) * m * vx1 * vy0;
        W.z = (1.f - wx) * wy * m * vx0 * vy1;
        W.w = wx * wy * m * vx1 * vy1;

        int x0c = min(max(x0, 0), WWD - 1);
        int x1c = min(max(x0 + 1, 0), WWD - 1);
        int y0c = min(max(y0, 0), HH - 1);
        int y1c = min(max(y0 + 1, 0), HH - 1);

        int4 O;
        O.x = (y0c * WWD + x0c) * (NCAT * 4);
        O.y = (y0c * WWD + x1c) * (NCAT * 4);
        O.z = (y1c * WWD + x0c) * (NCAT * 4);
        O.w = (y1c * WWD + x1c) * (NCAT * 4);

        s_wgt[qq][g][p] = W;
        s_idx[qq][g][p] = O;
    }
    __syncthreads();

    int qi = tid >> 6;
    int s  = tid & 63;
    int g  = s >> 4;
    int c4 = s & 15;
    int q = qbase + qi;
    int n = q >> 12;

    const char* vb = (const char*)(vom + (size_t)(n * LQ) * NCAT + g * 64 + c4 * 4);

    float4 acc = make_float4(0.f, 0.f, 0.f, 0.f);
#pragma unroll
    for (int p = 0; p < 9; ++p) {
        float4 W = s_wgt[qi][g][p];
        int4   O = s_idx[qi][g][p];

        float4 v00 = *(const float4*)(vb + O.x);
        float4 v10 = *(const float4*)(vb + O.y);
        float4 v01 = *(const float4*)(vb + O.z);
        float4 v11 = *(const float4*)(vb + O.w);

        acc.x = fmaf(W.x, v00.x, acc.x); acc.y = fmaf(W.x, v00.y, acc.y);
        acc.z = fmaf(W.x, v00.z, acc.z); acc.w = fmaf(W.x, v00.w, acc.w);
        acc.x = fmaf(W.y, v10.x, acc.x); acc.y = fmaf(W.y, v10.y, acc.y);
        acc.z = fmaf(W.y, v10.z, acc.z); acc.w = fmaf(W.y, v10.w, acc.w);
        acc.x = fmaf(W.z, v01.x, acc.x); acc.y = fmaf(W.z, v01.y, acc.y);
        acc.z = fmaf(W.z, v01.z, acc.z); acc.w = fmaf(W.z, v01.w, acc.w);
        acc.x = fmaf(W.w, v11.x, acc.x); acc.y = fmaf(W.w, v11.y, acc.y);
        acc.z = fmaf(W.w, v11.z, acc.z); acc.w = fmaf(W.w, v11.w, acc.w);
    }

    acc.x = tf32r(acc.x); acc.y = tf32r(acc.y);
    acc.z = tf32r(acc.z); acc.w = tf32r(acc.w);
    *(float4*)(smp + (size_t)q * CHN + g * 64 + c4 * 4) = acc;
}

// ---------------------------------------------------------------------------
extern "C" void kernel_launch(void* const* d_in, const int* in_sizes, int n_in,
                              void* d_out, int out_size)
{
    const float* x        = (const float*)d_in[0];
    const float* w_value  = (const float*)d_in[1];
    const float* b_value  = (const float*)d_in[2];
    const float* w_offset = (const float*)d_in[3];
    const float* b_offset = (const float*)d_in[4];
    const float* w_mask   = (const float*)d_in[5];
    const float* b_mask   = (const float*)d_in[6];
    const float* w_out    = (const float*)d_in[7];
    const float* b_out    = (const float*)d_in[8];
    float* out = (float*)d_out;

    float *vom, *smp, *bcat, *bp1, *bp2;
    cudaGetSymbolAddress((void**)&vom,  g_vom);
    cudaGetSymbolAddress((void**)&smp,  g_smp);
    cudaGetSymbolAddress((void**)&bcat, g_bcat);
    cudaGetSymbolAddress((void**)&bp1,  g_bp1);
    cudaGetSymbolAddress((void**)&bp2,  g_bp2);

    cudaFuncSetAttribute(gemm_mma<1>, cudaFuncAttributeMaxDynamicSharedMemorySize,
                         GEMM_SMEM_BYTES);
    cudaFuncSetAttribute(gemm_mma<0>, cudaFuncAttributeMaxDynamicSharedMemorySize,
                         GEMM_SMEM_BYTES);

    int pack_elems = NCAT * KDIM + CHN * KDIM + NCAT;
    pack_weights<<<(pack_elems + 255) / 256, 256>>>(w_value, b_value, w_offset,
                                                    b_offset, w_mask, b_mask, w_out);

    // GEMM-1: x(32768,256) @ [wv|wo|wm](256,384) + bcat -> vom (ldc=384); rounds A
    gemm_mma<1><<<dim3(NCAT / 128, MROWS / 256), 256, GEMM_SMEM_BYTES>>>(x, bp1, bcat,
                                                                         vom, NCAT);

    // DCNv4 sampling -> smp(32768,256), tf32-rounded on store
    dcn_sample<<<MROWS / 4, 256>>>(vom, smp);

    // GEMM-2: smp(32768,256) @ w_out(256,256) + b_out -> out (ldc=256)
    gemm_mma<0><<<dim3(CHN / 128, MROWS / 256), 256, GEMM_SMEM_BYTES>>>(smp, bp2, b_out,
                                                                        out, CHN);
}

// round 9
// speedup vs baseline: 1.1989x; 1.1618x over previous
#include <cuda_runtime.h>
#include <cuda_fp16.h>
#include <cstdint>

#define NB   8
#define HH   64
#define WWD  64
#define LQ   4096
#define CHN  256
#define NCAT 384
#define MROWS (NB * LQ)           // 32768
#define KDIM 256
#define PADK 40                   // A fp32 smem row stride (floats)
#define PADH 40                   // half smem row stride (halves)

#define A32_BYTES (256 * PADK * 4)    // 40960 per stage (fp32 A)
#define A16_BYTES (256 * PADH * 2)    // 20480 per stage (half A)
#define B16_BYTES (128 * PADH * 2)    // 10240 per stage
#define SMEM1_BYTES (2 * A32_BYTES + 2 * B16_BYTES)   // 102400 (GEMM-1)
#define SMEM2_BYTES (2 * A16_BYTES + 2 * B16_BYTES)   // 61440  (GEMM-2)

// ---- scratch (device globals; no allocation allowed) ----
__device__ float  g_bcat[NCAT];
__device__ float  g_vom[(size_t)MROWS * NCAT];
__device__ __half g_smp[(size_t)MROWS * CHN];
__device__ __half g_bp1[NCAT * KDIM];   // GEMM-1 B, col-major [n][k], half
__device__ __half g_bp2[CHN * KDIM];    // GEMM-2 B, col-major [n][k], half

__device__ __forceinline__ void cpasync16(uint32_t dst, const void* src) {
    asm volatile("cp.async.ca.shared.global [%0], [%1], 16;"
                 :: "r"(dst), "l"(src));
}
__device__ __forceinline__ uint32_t pack_h2(float lo, float hi) {
    uint32_t r;
    asm("cvt.rn.f16x2.f32 %0, %1, %2;" : "=r"(r) : "f"(hi), "f"(lo));
    return r;
}

// ---------------------------------------------------------------------------
// Pack weights to half (col-major [n][k]) + concat biases (fp32).
// ---------------------------------------------------------------------------
__global__ void pack_weights(const float* __restrict__ wv, const float* __restrict__ bv,
                             const float* __restrict__ wo, const float* __restrict__ bo,
                             const float* __restrict__ wm, const float* __restrict__ bm,
                             const float* __restrict__ wout)
{
    int idx = blockIdx.x * 256 + threadIdx.x;
    if (idx < NCAT * KDIM) {
        int n = idx >> 8, k = idx & 255;
        float val = 0.f;
        if (n < 256)      val = wv[k * 256 + n];
        else if (n < 328) val = wo[k * 72 + (n - 256)];
        else if (n < 364) val = wm[k * 36 + (n - 328)];
        g_bp1[idx] = __float2half_rn(val);
    } else if (idx < NCAT * KDIM + CHN * KDIM) {
        int j = idx - NCAT * KDIM;
        int n = j >> 8, k = j & 255;
        g_bp2[j] = __float2half_rn(wout[k * 256 + n]);
    } else if (idx < NCAT * KDIM + CHN * KDIM + NCAT) {
        int c = idx - (NCAT * KDIM + CHN * KDIM);
        float val = 0.f;
        if (c < 256)      val = bv[c];
        else if (c < 328) val = bo[c - 256];
        else if (c < 364) val = bm[c - 328];
        g_bcat[c] = val;
    }
}

// ---------------------------------------------------------------------------
// fp16 mma.sync GEMM (m16n8k16, fp32 accumulate), cp.async double-buffered,
// one sync per 32-K chunk.  C(M,N) = A(M,256) @ B^T + bias.
// HALF_A=0: A is fp32 in gmem+smem; fragments converted via cvt.rn.f16x2.f32.
// HALF_A=1: A is half in gmem+smem; fragments are direct LDS.32.
// CTA tile 256x128, 8 warps (4m x 2n), warp tile 64x64, BK=32.
// ---------------------------------------------------------------------------
template<int HALF_A>
__global__ __launch_bounds__(256) void gemm_mma(const void* __restrict__ Avp,
                                                const __half* __restrict__ Bh,
                                                const float* __restrict__ bias,
                                                float* __restrict__ C, int ldc)
{
    extern __shared__ char smem[];
    uint32_t sbase = (uint32_t)__cvta_generic_to_shared(smem);
    const int ABYTES = HALF_A ? A16_BYTES : A32_BYTES;

    int tid = threadIdx.x;
    int warp = tid >> 5, lane = tid & 31;
    int wmi = warp >> 1;          // 0..3 (M, 64-row tiles)
    int wni = warp & 1;           // 0..1 (N, 64-col tiles)
    int gid = lane >> 2, tg = lane & 3;

    float acc[4][8][4];
#pragma unroll
    for (int mt = 0; mt < 4; ++mt)
#pragma unroll
        for (int nt = 0; nt < 8; ++nt)
#pragma unroll
            for (int i = 0; i < 4; ++i) acc[mt][nt][i] = 0.f;

    const float*  Af = (const float*)Avp  + (size_t)blockIdx.y * 256 * KDIM;
    const __half* Ah = (const __half*)Avp + (size_t)blockIdx.y * 256 * KDIM;
    const __half* Bb = Bh + (size_t)blockIdx.x * 128 * KDIM;

    auto issue = [&](int c, int b) {
        uint32_t adst = sbase + (uint32_t)(b * ABYTES);
        uint32_t bdst = sbase + (uint32_t)(2 * ABYTES + b * B16_BYTES);
        if (HALF_A) {
            // A: 256 rows x 32 halves (64 B/row) = 1024 x 16B; 4 per thread
#pragma unroll
            for (int j = 0; j < 4; ++j) {
                int s = j * 256 + tid;
                int r = s >> 2, q = (s & 3) * 8;         // q in halves
                cpasync16(adst + (uint32_t)(r * PADH + q) * 2,
                          Ah + (size_t)r * KDIM + c * 32 + q);
            }
        } else {
            // A: 256 rows x 32 floats (128 B/row) = 2048 x 16B; 8 per thread
            int r0 = tid >> 3, q0 = (tid & 7) * 4;       // q in floats
#pragma unroll
            for (int j = 0; j < 8; ++j) {
                int r = r0 + j * 32;
                cpasync16(adst + (uint32_t)(r * PADK + q0) * 4,
                          Af + (size_t)r * KDIM + c * 32 + q0);
            }
        }
        // B: 128 rows x 32 halves = 512 x 16B; 2 per thread
#pragma unroll
        for (int j = 0; j < 2; ++j) {
            int s = j * 256 + tid;
            int r = s >> 2, q = (s & 3) * 8;
            cpasync16(bdst + (uint32_t)(r * PADH + q) * 2,
                      Bb + (size_t)r * KDIM + c * 32 + q);
        }
        asm volatile("cp.async.commit_group;" ::: "memory");
    };

    issue(0, 0);

    for (int c = 0; c < 8; ++c) {
        int b = c & 1;
        asm volatile("cp.async.wait_group 0;" ::: "memory");
        __syncthreads();                      // tile c visible; all warps done with c-1
        if (c < 7) issue(c + 1, b ^ 1);       // prefetch overlaps compute(c)

        const float*  As32 = (const float*)(smem + b * ABYTES);
        const __half* As16 = (const __half*)(smem + b * ABYTES);
        const __half* Bs   = (const __half*)(smem + 2 * ABYTES + b * B16_BYTES);

#pragma unroll
        for (int ks = 0; ks < 2; ++ks) {
            int kb = ks * 16;
            uint32_t a[4][4], bf[8][2];
#pragma unroll
            for (int mt = 0; mt < 4; ++mt) {
                int row = wmi * 64 + mt * 16;
                if (HALF_A) {
                    a[mt][0] = *(const uint32_t*)&As16[(row + gid)     * PADH + kb + 2 * tg];
                    a[mt][1] = *(const uint32_t*)&As16[(row + gid + 8) * PADH + kb + 2 * tg];
                    a[mt][2] = *(const uint32_t*)&As16[(row + gid)     * PADH + kb + 2 * tg + 8];
                    a[mt][3] = *(const uint32_t*)&As16[(row + gid + 8) * PADH + kb + 2 * tg + 8];
                } else {
                    float2 e0 = *(const float2*)&As32[(row + gid)     * PADK + kb + 2 * tg];
                    float2 e1 = *(const float2*)&As32[(row + gid + 8) * PADK + kb + 2 * tg];
                    float2 e2 = *(const float2*)&As32[(row + gid)     * PADK + kb + 2 * tg + 8];
                    float2 e3 = *(const float2*)&As32[(row + gid + 8) * PADK + kb + 2 * tg + 8];
                    a[mt][0] = pack_h2(e0.x, e0.y);
                    a[mt][1] = pack_h2(e1.x, e1.y);
                    a[mt][2] = pack_h2(e2.x, e2.y);
                    a[mt][3] = pack_h2(e3.x, e3.y);
                }
            }
#pragma unroll
            for (int nt = 0; nt < 8; ++nt) {
                int n = wni * 64 + nt * 8 + gid;
                bf[nt][0] = *(const uint32_t*)&Bs[n * PADH + kb + 2 * tg];
                bf[nt][1] = *(const uint32_t*)&Bs[n * PADH + kb + 2 * tg + 8];
            }
#pragma unroll
            for (int mt = 0; mt < 4; ++mt)
#pragma unroll
                for (int nt = 0; nt < 8; ++nt) {
                    asm volatile(
                        "mma.sync.aligned.m16n8k16.row.col.f32.f16.f16.f32 "
                        "{%0,%1,%2,%3}, {%4,%5,%6,%7}, {%8,%9}, {%0,%1,%2,%3};"
                        : "+f"(acc[mt][nt][0]), "+f"(acc[mt][nt][1]),
                          "+f"(acc[mt][nt][2]), "+f"(acc[mt][nt][3])
                        : "r"(a[mt][0]), "r"(a[mt][1]), "r"(a[mt][2]), "r"(a[mt][3]),
                          "r"(bf[nt][0]), "r"(bf[nt][1]));
                }
        }
    }

#pragma unroll
    for (int mt = 0; mt < 4; ++mt) {
#pragma unroll
        for (int i = 0; i < 2; ++i) {
            size_t row = (size_t)blockIdx.y * 256 + wmi * 64 + mt * 16 + gid + i * 8;
            float* Crow = C + row * (size_t)ldc;
#pragma unroll
            for (int nt = 0; nt < 8; ++nt) {
                int col = blockIdx.x * 128 + wni * 64 + nt * 8 + 2 * tg;
                float2 o;
                o.x = acc[mt][nt][2 * i + 0] + bias[col + 0];
                o.y = acc[mt][nt][2 * i + 1] + bias[col + 1];
                *(float2*)(&Crow[col]) = o;
            }
        }
    }
}

// ---------------------------------------------------------------------------
// DCNv4 bilinear sampling (logic unchanged); output stored as half for the
// fp16 GEMM-2 (eps 2^-11, same as previous tf32 store path).
// ---------------------------------------------------------------------------
__global__ __launch_bounds__(256) void dcn_sample(const float* __restrict__ vom,
                                                  __half* __restrict__ smp)
{
    int tid = threadIdx.x;
    int qbase = blockIdx.x * 4;

    __shared__ float4 s_wgt[4][4][9];
    __shared__ int4   s_idx[4][4][9];

    if (tid < 144) {
        int qq = tid / 36, u = tid % 36;
        int g = u / 9, p = u % 9;
        int q = qbase + qq;
        int hw = q & 4095, h = hw >> 6, w = hw & 63;
        const float* row = vom + (size_t)q * NCAT;
        float ox = row[256 + g * 18 + p * 2];
        float oy = row[256 + g * 18 + p * 2 + 1];
        float m  = row[328 + g * 9 + p];

        int ix = p / 3, iy = p % 3;
        float gx = (float)(w + ix - 1) + ox;
        float gy = (float)(h + iy - 1) + oy;

        float x0f = floorf(gx), y0f = floorf(gy);
        int x0 = (int)x0f, y0 = (int)y0f;
        float wx = gx - x0f, wy = gy - y0f;

        float vx0 = (x0 >= 0 && x0 < WWD) ? 1.f : 0.f;
        float vx1 = (x0 + 1 >= 0 && x0 + 1 < WWD) ? 1.f : 0.f;
        float vy0 = (y0 >= 0 && y0 < HH) ? 1.f : 0.f;
        float vy1 = (y0 + 1 >= 0 && y0 + 1 < HH) ? 1.f : 0.f;

        float4 W;
        W.x = (1.f - wx) * (1.f - wy) * m * vx0 * vy0;
        W.y = wx * (1.f - wy) * m * vx1 * vy0;
        W.z = (1.f - wx) * wy * m * vx0 * vy1;
        W.w = wx * wy * m * vx1 * vy1;

        int x0c = min(max(x0, 0), WWD - 1);
        int x1c = min(max(x0 + 1, 0), WWD - 1);
        int y0c = min(max(y0, 0), HH - 1);
        int y1c = min(max(y0 + 1, 0), HH - 1);

        int4 O;
        O.x = (y0c * WWD + x0c) * (NCAT * 4);
        O.y = (y0c * WWD + x1c) * (NCAT * 4);
        O.z = (y1c * WWD + x0c) * (NCAT * 4);
        O.w = (y1c * WWD + x1c) * (NCAT * 4);

        s_wgt[qq][g][p] = W;
        s_idx[qq][g][p] = O;
    }
    __syncthreads();

    int qi = tid >> 6;
    int s  = tid & 63;
    int g  = s >> 4;
    int c4 = s & 15;
    int q = qbase + qi;
    int n = q >> 12;

    const char* vb = (const char*)(vom + (size_t)(n * LQ) * NCAT + g * 64 + c4 * 4);

    float4 acc = make_float4(0.f, 0.f, 0.f, 0.f);
#pragma unroll
    for (int p = 0; p < 9; ++p) {
        float4 W = s_wgt[qi][g][p];
        int4   O = s_idx[qi][g][p];

        float4 v00 = *(const float4*)(vb + O.x);
        float4 v10 = *(const float4*)(vb + O.y);
        float4 v01 = *(const float4*)(vb + O.z);
        float4 v11 = *(const float4*)(vb + O.w);

        acc.x = fmaf(W.x, v00.x, acc.x); acc.y = fmaf(W.x, v00.y, acc.y);
        acc.z = fmaf(W.x, v00.z, acc.z); acc.w = fmaf(W.x, v00.w, acc.w);
        acc.x = fmaf(W.y, v10.x, acc.x); acc.y = fmaf(W.y, v10.y, acc.y);
        acc.z = fmaf(W.y, v10.z, acc.z); acc.w = fmaf(W.y, v10.w, acc.w);
        acc.x = fmaf(W.z, v01.x, acc.x); acc.y = fmaf(W.z, v01.y, acc.y);
        acc.z = fmaf(W.z, v01.z, acc.z); acc.w = fmaf(W.z, v01.w, acc.w);
        acc.x = fmaf(W.w, v11.x, acc.x); acc.y = fmaf(W.w, v11.y, acc.y);
        acc.z = fmaf(W.w, v11.z, acc.z); acc.w = fmaf(W.w, v11.w, acc.w);
    }

    uint2 o;
    o.x = pack_h2(acc.x, acc.y);
    o.y = pack_h2(acc.z, acc.w);
    *(uint2*)(smp + (size_t)q * CHN + g * 64 + c4 * 4) = o;
}

// ---------------------------------------------------------------------------
extern "C" void kernel_launch(void* const* d_in, const int* in_sizes, int n_in,
                              void* d_out, int out_size)
{
    const float* x        = (const float*)d_in[0];
    const float* w_value  = (const float*)d_in[1];
    const float* b_value  = (const float*)d_in[2];
    const float* w_offset = (const float*)d_in[3];
    const float* b_offset = (const float*)d_in[4];
    const float* w_mask   = (const float*)d_in[5];
    const float* b_mask   = (const float*)d_in[6];
    const float* w_out    = (const float*)d_in[7];
    const float* b_out    = (const float*)d_in[8];
    float* out = (float*)d_out;

    float *vom, *bcat;
    __half *smp, *bp1, *bp2;
    cudaGetSymbolAddress((void**)&vom,  g_vom);
    cudaGetSymbolAddress((void**)&smp,  g_smp);
    cudaGetSymbolAddress((void**)&bcat, g_bcat);
    cudaGetSymbolAddress((void**)&bp1,  g_bp1);
    cudaGetSymbolAddress((void**)&bp2,  g_bp2);

    cudaFuncSetAttribute(gemm_mma<0>, cudaFuncAttributeMaxDynamicSharedMemorySize,
                         SMEM1_BYTES);
    cudaFuncSetAttribute(gemm_mma<1>, cudaFuncAttributeMaxDynamicSharedMemorySize,
                         SMEM2_BYTES);

    int pack_elems = NCAT * KDIM + CHN * KDIM + NCAT;
    pack_weights<<<(pack_elems + 255) / 256, 256>>>(w_value, b_value, w_offset,
                                                    b_offset, w_mask, b_mask, w_out);

    // GEMM-1: x(32768,256) fp32 @ [wv|wo|wm] half -> vom fp32 (ldc=384)
    gemm_mma<0><<<dim3(NCAT / 128, MROWS / 256), 256, SMEM1_BYTES>>>(x, bp1, bcat,
                                                                     vom, NCAT);

    // DCNv4 sampling -> smp(32768,256) half
    dcn_sample<<<MROWS / 4, 256>>>(vom, smp);

    // GEMM-2: smp half @ w_out half + b_out -> out fp32 (ldc=256)
    gemm_mma<1><<<dim3(CHN / 128, MROWS / 256), 256, SMEM2_BYTES>>>(smp, bp2, b_out,
                                                                    out, CHN);
}

// round 10
// speedup vs baseline: 1.4099x; 1.1760x over previous
#include <cuda_runtime.h>
#include <cuda_fp16.h>
#include <cstdint>

#define NB   8
#define HH   64
#define WWD  64
#define LQ   4096
#define CHN  256
#define NCAT 384
#define MROWS (NB * LQ)           // 32768
#define KDIM 256
#define PADK 40                   // A fp32 smem row stride (floats)
#define PADH 40                   // half smem row stride (halves)

#define A32_BYTES (256 * PADK * 4)    // 40960 per stage (fp32 A)
#define A16_BYTES (256 * PADH * 2)    // 20480 per stage (half A)
#define B16_BYTES (128 * PADH * 2)    // 10240 per stage
#define SMEM1_BYTES (2 * A32_BYTES + 2 * B16_BYTES)   // 102400 (GEMM-1)
#define SMEM2_BYTES (2 * A16_BYTES + 2 * B16_BYTES)   // 61440  (GEMM-2)

// ---- scratch (device globals; no allocation allowed) ----
__device__ float  g_bcat[NCAT];
__device__ __half g_vh[(size_t)MROWS * CHN];    // value tensor, half
__device__ float  g_om[(size_t)MROWS * 128];    // offset(72)+mask(36)+pad, fp32
__device__ __half g_smp[(size_t)MROWS * CHN];
__device__ __half g_bp1[NCAT * KDIM];   // GEMM-1 B, col-major [n][k], half
__device__ __half g_bp2[CHN * KDIM];    // GEMM-2 B, col-major [n][k], half

__device__ __forceinline__ void cpasync16(uint32_t dst, const void* src) {
    asm volatile("cp.async.ca.shared.global [%0], [%1], 16;"
                 :: "r"(dst), "l"(src));
}
__device__ __forceinline__ uint32_t pack_h2(float lo, float hi) {
    uint32_t r;
    asm("cvt.rn.f16x2.f32 %0, %1, %2;" : "=r"(r) : "f"(hi), "f"(lo));
    return r;
}

// ---------------------------------------------------------------------------
// Pack weights to half (col-major [n][k]) + concat biases (fp32).
// ---------------------------------------------------------------------------
__global__ void pack_weights(const float* __restrict__ wv, const float* __restrict__ bv,
                             const float* __restrict__ wo, const float* __restrict__ bo,
                             const float* __restrict__ wm, const float* __restrict__ bm,
                             const float* __restrict__ wout)
{
    int idx = blockIdx.x * 256 + threadIdx.x;
    if (idx < NCAT * KDIM) {
        int n = idx >> 8, k = idx & 255;
        float val = 0.f;
        if (n < 256)      val = wv[k * 256 + n];
        else if (n < 328) val = wo[k * 72 + (n - 256)];
        else if (n < 364) val = wm[k * 36 + (n - 328)];
        g_bp1[idx] = __float2half_rn(val);
    } else if (idx < NCAT * KDIM + CHN * KDIM) {
        int j = idx - NCAT * KDIM;
        int n = j >> 8, k = j & 255;
        g_bp2[j] = __float2half_rn(wout[k * 256 + n]);
    } else if (idx < NCAT * KDIM + CHN * KDIM + NCAT) {
        int c = idx - (NCAT * KDIM + CHN * KDIM);
        float val = 0.f;
        if (c < 256)      val = bv[c];
        else if (c < 328) val = bo[c - 256];
        else if (c < 364) val = bm[c - 328];
        g_bcat[c] = val;
    }
}

// ===========================================================================
// GEMM core (shared by both kernels): fp16 m16n8k16, fp32 accum,
// cp.async double-buffered, one sync per 32-K chunk.
// CTA tile 256x128, 8 warps (4m x 2n), warp tile 64x64.
// ===========================================================================
template<int HALF_A>
__device__ __forceinline__ void gemm_core(const void* Avp, const __half* Bb,
                                          char* smem, float acc[4][8][4])
{
    uint32_t sbase = (uint32_t)__cvta_generic_to_shared(smem);
    const int ABYTES = HALF_A ? A16_BYTES : A32_BYTES;
    int tid = threadIdx.x;
    int warp = tid >> 5, lane = tid & 31;
    int wmi = warp >> 1, wni = warp & 1;
    int gid = lane >> 2, tg = lane & 3;

    const float*  Af = (const float*)Avp;
    const __half* Ah = (const __half*)Avp;

    auto issue = [&](int c, int b) {
        uint32_t adst = sbase + (uint32_t)(b * ABYTES);
        uint32_t bdst = sbase + (uint32_t)(2 * ABYTES + b * B16_BYTES);
        if (HALF_A) {
#pragma unroll
            for (int j = 0; j < 4; ++j) {
                int s = j * 256 + tid;
                int r = s >> 2, q = (s & 3) * 8;
                cpasync16(adst + (uint32_t)(r * PADH + q) * 2,
                          Ah + (size_t)r * KDIM + c * 32 + q);
            }
        } else {
            int r0 = tid >> 3, q0 = (tid & 7) * 4;
#pragma unroll
            for (int j = 0; j < 8; ++j) {
                int r = r0 + j * 32;
                cpasync16(adst + (uint32_t)(r * PADK + q0) * 4,
                          Af + (size_t)r * KDIM + c * 32 + q0);
            }
        }
#pragma unroll
        for (int j = 0; j < 2; ++j) {
            int s = j * 256 + tid;
            int r = s >> 2, q = (s & 3) * 8;
            cpasync16(bdst + (uint32_t)(r * PADH + q) * 2,
                      Bb + (size_t)r * KDIM + c * 32 + q);
        }
        asm volatile("cp.async.commit_group;" ::: "memory");
    };

    issue(0, 0);

    for (int c = 0; c < 8; ++c) {
        int b = c & 1;
        asm volatile("cp.async.wait_group 0;" ::: "memory");
        __syncthreads();
        if (c < 7) issue(c + 1, b ^ 1);

        const float*  As32 = (const float*)(smem + b * ABYTES);
        const __half* As16 = (const __half*)(smem + b * ABYTES);
        const __half* Bs   = (const __half*)(smem + 2 * ABYTES + b * B16_BYTES);

#pragma unroll
        for (int ks = 0; ks < 2; ++ks) {
            int kb = ks * 16;
            uint32_t a[4][4], bf[8][2];
#pragma unroll
            for (int mt = 0; mt < 4; ++mt) {
                int row = wmi * 64 + mt * 16;
                if (HALF_A) {
                    a[mt][0] = *(const uint32_t*)&As16[(row + gid)     * PADH + kb + 2 * tg];
                    a[mt][1] = *(const uint32_t*)&As16[(row + gid + 8) * PADH + kb + 2 * tg];
                    a[mt][2] = *(const uint32_t*)&As16[(row + gid)     * PADH + kb + 2 * tg + 8];
                    a[mt][3] = *(const uint32_t*)&As16[(row + gid + 8) * PADH + kb + 2 * tg + 8];
                } else {
                    float2 e0 = *(const float2*)&As32[(row + gid)     * PADK + kb + 2 * tg];
                    float2 e1 = *(const float2*)&As32[(row + gid + 8) * PADK + kb + 2 * tg];
                    float2 e2 = *(const float2*)&As32[(row + gid)     * PADK + kb + 2 * tg + 8];
                    float2 e3 = *(const float2*)&As32[(row + gid + 8) * PADK + kb + 2 * tg + 8];
                    a[mt][0] = pack_h2(e0.x, e0.y);
                    a[mt][1] = pack_h2(e1.x, e1.y);
                    a[mt][2] = pack_h2(e2.x, e2.y);
                    a[mt][3] = pack_h2(e3.x, e3.y);
                }
            }
#pragma unroll
            for (int nt = 0; nt < 8; ++nt) {
                int n = wni * 64 + nt * 8 + gid;
                bf[nt][0] = *(const uint32_t*)&Bs[n * PADH + kb + 2 * tg];
                bf[nt][1] = *(const uint32_t*)&Bs[n * PADH + kb + 2 * tg + 8];
            }
#pragma unroll
            for (int mt = 0; mt < 4; ++mt)
#pragma unroll
                for (int nt = 0; nt < 8; ++nt) {
                    asm volatile(
                        "mma.sync.aligned.m16n8k16.row.col.f32.f16.f16.f32 "
                        "{%0,%1,%2,%3}, {%4,%5,%6,%7}, {%8,%9}, {%0,%1,%2,%3};"
                        : "+f"(acc[mt][nt][0]), "+f"(acc[mt][nt][1]),
                          "+f"(acc[mt][nt][2]), "+f"(acc[mt][nt][3])
                        : "r"(a[mt][0]), "r"(a[mt][1]), "r"(a[mt][2]), "r"(a[mt][3]),
                          "r"(bf[nt][0]), "r"(bf[nt][1]));
                }
        }
    }
}

// ---------------------------------------------------------------------------
// GEMM-1: x(M,256) fp32 @ bp1 half -> split output:
//   N-tiles 0-1 (values)  -> g_vh half (ld 256)
//   N-tile 2 (off/mask)   -> g_om fp32 (ld 128)
// ---------------------------------------------------------------------------
__global__ __launch_bounds__(256) void gemm1(const float* __restrict__ A,
                                             const __half* __restrict__ Bh,
                                             const float* __restrict__ bias,
                                             __half* __restrict__ vh,
                                             float* __restrict__ om)
{
    extern __shared__ char smem[];
    float acc[4][8][4];
#pragma unroll
    for (int mt = 0; mt < 4; ++mt)
#pragma unroll
        for (int nt = 0; nt < 8; ++nt)
#pragma unroll
            for (int i = 0; i < 4; ++i) acc[mt][nt][i] = 0.f;

    gemm_core<0>(A + (size_t)blockIdx.y * 256 * KDIM,
                 Bh + (size_t)blockIdx.x * 128 * KDIM, smem, acc);

    int tid = threadIdx.x;
    int warp = tid >> 5, lane = tid & 31;
    int wmi = warp >> 1, wni = warp & 1;
    int gid = lane >> 2, tg = lane & 3;
    bool is_val = (blockIdx.x < 2);

#pragma unroll
    for (int mt = 0; mt < 4; ++mt) {
#pragma unroll
        for (int i = 0; i < 2; ++i) {
            size_t row = (size_t)blockIdx.y * 256 + wmi * 64 + mt * 16 + gid + i * 8;
#pragma unroll
            for (int nt = 0; nt < 8; ++nt) {
                int col = blockIdx.x * 128 + wni * 64 + nt * 8 + 2 * tg;
                float ox = acc[mt][nt][2 * i + 0] + bias[col + 0];
                float oy = acc[mt][nt][2 * i + 1] + bias[col + 1];
                if (is_val) {
                    *(uint32_t*)(vh + row * CHN + col) = pack_h2(ox, oy);
                } else {
                    float2 o = make_float2(ox, oy);
                    *(float2*)(om + row * 128 + (col - 256)) = o;
                }
            }
        }
    }
}

// ---------------------------------------------------------------------------
// GEMM-2: smp(M,256) half @ bp2 half + b_out -> out fp32 (ld 256)
// ---------------------------------------------------------------------------
__global__ __launch_bounds__(256) void gemm2(const __half* __restrict__ A,
                                             const __half* __restrict__ Bh,
                                             const float* __restrict__ bias,
                                             float* __restrict__ C)
{
    extern __shared__ char smem[];
    float acc[4][8][4];
#pragma unroll
    for (int mt = 0; mt < 4; ++mt)
#pragma unroll
        for (int nt = 0; nt < 8; ++nt)
#pragma unroll
            for (int i = 0; i < 4; ++i) acc[mt][nt][i] = 0.f;

    gemm_core<1>(A + (size_t)blockIdx.y * 256 * KDIM,
                 Bh + (size_t)blockIdx.x * 128 * KDIM, smem, acc);

    int tid = threadIdx.x;
    int warp = tid >> 5, lane = tid & 31;
    int wmi = warp >> 1, wni = warp & 1;
    int gid = lane >> 2, tg = lane & 3;

#pragma unroll
    for (int mt = 0; mt < 4; ++mt) {
#pragma unroll
        for (int i = 0; i < 2; ++i) {
            size_t row = (size_t)blockIdx.y * 256 + wmi * 64 + mt * 16 + gid + i * 8;
            float* Crow = C + row * (size_t)CHN;
#pragma unroll
            for (int nt = 0; nt < 8; ++nt) {
                int col = blockIdx.x * 128 + wni * 64 + nt * 8 + 2 * tg;
                float2 o;
                o.x = acc[mt][nt][2 * i + 0] + bias[col + 0];
                o.y = acc[mt][nt][2 * i + 1] + bias[col + 1];
                *(float2*)(&Crow[col]) = o;
            }
        }
    }
}

// ---------------------------------------------------------------------------
// DCNv4 bilinear sampling on HALF values. 4 queries per 256-thread block.
// Precompute (144 thr): weights (validity+mask folded) + byte offsets from
// fp32 g_om. Gather: 4x LDG.64 (half4) + cvt + fp32 FMA per point.
// ---------------------------------------------------------------------------
__global__ __launch_bounds__(256) void dcn_sample(const __half* __restrict__ vh,
                                                  const float* __restrict__ om,
                                                  __half* __restrict__ smp)
{
    int tid = threadIdx.x;
    int qbase = blockIdx.x * 4;

    __shared__ float4 s_wgt[4][4][9];
    __shared__ int4   s_idx[4][4][9];

    if (tid < 144) {
        int qq = tid / 36, u = tid % 36;
        int g = u / 9, p = u % 9;
        int q = qbase + qq;
        int hw = q & 4095, h = hw >> 6, w = hw & 63;
        const float* row = om + (size_t)q * 128;
        float ox = row[g * 18 + p * 2];
        float oy = row[g * 18 + p * 2 + 1];
        float m  = row[72 + g * 9 + p];

        int ix = p / 3, iy = p % 3;
        float gx = (float)(w + ix - 1) + ox;
        float gy = (float)(h + iy - 1) + oy;

        float x0f = floorf(gx), y0f = floorf(gy);
        int x0 = (int)x0f, y0 = (int)y0f;
        float wx = gx - x0f, wy = gy - y0f;

        float vx0 = (x0 >= 0 && x0 < WWD) ? 1.f : 0.f;
        float vx1 = (x0 + 1 >= 0 && x0 + 1 < WWD) ? 1.f : 0.f;
        float vy0 = (y0 >= 0 && y0 < HH) ? 1.f : 0.f;
        float vy1 = (y0 + 1 >= 0 && y0 + 1 < HH) ? 1.f : 0.f;

        float4 W;
        W.x = (1.f - wx) * (1.f - wy) * m * vx0 * vy0;
        W.y = wx * (1.f - wy) * m * vx1 * vy0;
        W.z = (1.f - wx) * wy * m * vx0 * vy1;
        W.w = wx * wy * m * vx1 * vy1;

        int x0c = min(max(x0, 0), WWD - 1);
        int x1c = min(max(x0 + 1, 0), WWD - 1);
        int y0c = min(max(y0, 0), HH - 1);
        int y1c = min(max(y0 + 1, 0), HH - 1);

        int4 O;                                     // byte offsets (half row = 512B)
        O.x = (y0c * WWD + x0c) * (CHN * 2);
        O.y = (y0c * WWD + x1c) * (CHN * 2);
        O.z = (y1c * WWD + x0c) * (CHN * 2);
        O.w = (y1c * WWD + x1c) * (CHN * 2);

        s_wgt[qq][g][p] = W;
        s_idx[qq][g][p] = O;
    }
    __syncthreads();

    int qi = tid >> 6;
    int s  = tid & 63;
    int g  = s >> 4;
    int c4 = s & 15;
    int q = qbase + qi;
    int n = q >> 12;

    const char* vb = (const char*)(vh + (size_t)(n * LQ) * CHN + g * 64 + c4 * 4);

    float4 acc = make_float4(0.f, 0.f, 0.f, 0.f);
#pragma unroll
    for (int p = 0; p < 9; ++p) {
        float4 W = s_wgt[qi][g][p];
        int4   O = s_idx[qi][g][p];

        uint2 r00 = *(const uint2*)(vb + O.x);
        uint2 r10 = *(const uint2*)(vb + O.y);
        uint2 r01 = *(const uint2*)(vb + O.z);
        uint2 r11 = *(const uint2*)(vb + O.w);

        float2 a0, a1;
        a0 = __half22float2(*(__half2*)&r00.x); a1 = __half22float2(*(__half2*)&r00.y);
        acc.x = fmaf(W.x, a0.x, acc.x); acc.y = fmaf(W.x, a0.y, acc.y);
        acc.z = fmaf(W.x, a1.x, acc.z); acc.w = fmaf(W.x, a1.y, acc.w);
        a0 = __half22float2(*(__half2*)&r10.x); a1 = __half22float2(*(__half2*)&r10.y);
        acc.x = fmaf(W.y, a0.x, acc.x); acc.y = fmaf(W.y, a0.y, acc.y);
        acc.z = fmaf(W.y, a1.x, acc.z); acc.w = fmaf(W.y, a1.y, acc.w);
        a0 = __half22float2(*(__half2*)&r01.x); a1 = __half22float2(*(__half2*)&r01.y);
        acc.x = fmaf(W.z, a0.x, acc.x); acc.y = fmaf(W.z, a0.y, acc.y);
        acc.z = fmaf(W.z, a1.x, acc.z); acc.w = fmaf(W.z, a1.y, acc.w);
        a0 = __half22float2(*(__half2*)&r11.x); a1 = __half22float2(*(__half2*)&r11.y);
        acc.x = fmaf(W.w, a0.x, acc.x); acc.y = fmaf(W.w, a0.y, acc.y);
        acc.z = fmaf(W.w, a1.x, acc.z); acc.w = fmaf(W.w, a1.y, acc.w);
    }

    uint2 o;
    o.x = pack_h2(acc.x, acc.y);
    o.y = pack_h2(acc.z, acc.w);
    *(uint2*)(smp + (size_t)q * CHN + g * 64 + c4 * 4) = o;
}

// ---------------------------------------------------------------------------
extern "C" void kernel_launch(void* const* d_in, const int* in_sizes, int n_in,
                              void* d_out, int out_size)
{
    const float* x        = (const float*)d_in[0];
    const float* w_value  = (const float*)d_in[1];
    const float* b_value  = (const float*)d_in[2];
    const float* w_offset = (const float*)d_in[3];
    const float* b_offset = (const float*)d_in[4];
    const float* w_mask   = (const float*)d_in[5];
    const float* b_mask   = (const float*)d_in[6];
    const float* w_out    = (const float*)d_in[7];
    const float* b_out    = (const float*)d_in[8];
    float* out = (float*)d_out;

    float *bcat, *om;
    __half *vh, *smp, *bp1, *bp2;
    cudaGetSymbolAddress((void**)&vh,   g_vh);
    cudaGetSymbolAddress((void**)&om,   g_om);
    cudaGetSymbolAddress((void**)&smp,  g_smp);
    cudaGetSymbolAddress((void**)&bcat, g_bcat);
    cudaGetSymbolAddress((void**)&bp1,  g_bp1);
    cudaGetSymbolAddress((void**)&bp2,  g_bp2);

    cudaFuncSetAttribute(gemm1, cudaFuncAttributeMaxDynamicSharedMemorySize,
                         SMEM1_BYTES);
    cudaFuncSetAttribute(gemm2, cudaFuncAttributeMaxDynamicSharedMemorySize,
                         SMEM2_BYTES);

    int pack_elems = NCAT * KDIM + CHN * KDIM + NCAT;
    pack_weights<<<(pack_elems + 255) / 256, 256>>>(w_value, b_value, w_offset,
                                                    b_offset, w_mask, b_mask, w_out);

    // GEMM-1: x fp32 @ bp1 half -> vh (half) + om (fp32)
    gemm1<<<dim3(NCAT / 128, MROWS / 256), 256, SMEM1_BYTES>>>(x, bp1, bcat, vh, om);

    // DCNv4 sampling on half values -> smp half
    dcn_sample<<<MROWS / 4, 256>>>(vh, om, smp);

    // GEMM-2: smp half @ w_out half + b_out -> out fp32
    gemm2<<<dim3(CHN / 128, MROWS / 256), 256, SMEM2_BYTES>>>(smp, bp2, b_out, out);
}